// round 2
// baseline (speedup 1.0000x reference)
#include <cuda_runtime.h>
#include <cuda_fp16.h>

#define VOCAB 100000
#define EMB 128

// Precomputed normalized embedding table: E[v][j] = normalize(W[:,v] + b)[j], fp16.
// 100000 * 128 * 2B = 25.6 MB (static __device__ scratch, allowed).
__device__ __half g_E[(size_t)VOCAB * EMB];

// ---------------------------------------------------------------------------
// Kernel 1: build the normalized embedding table.
// One warp per vocab entry v; 8 warps (8 consecutive v) per block so the
// stride-VOCAB column reads of W share 32B sectors across warps via L1.
// ---------------------------------------------------------------------------
__global__ void build_table_kernel(const float* __restrict__ W,
                                   const float* __restrict__ b) {
    int warp = threadIdx.x >> 5;
    int lane = threadIdx.x & 31;
    int v = blockIdx.x * 8 + warp;
    if (v >= VOCAB) return;

    float vals[4];
    float ss = 0.f;
#pragma unroll
    for (int k = 0; k < 4; k++) {
        int j = lane * 4 + k;                       // 4 consecutive emb dims per lane
        float e = W[(size_t)j * VOCAB + v] + __ldg(&b[j]);
        vals[k] = e;
        ss = fmaf(e, e, ss);
    }
    // warp reduce sum of squares
#pragma unroll
    for (int o = 16; o > 0; o >>= 1)
        ss += __shfl_xor_sync(0xffffffffu, ss, o);

    float inv = 1.0f / fmaxf(sqrtf(ss), 1e-12f);    // torch F.normalize eps

    union { __half2 h[2]; uint2 u; } pk;
    pk.h[0] = __floats2half2_rn(vals[0] * inv, vals[1] * inv);
    pk.h[1] = __floats2half2_rn(vals[2] * inv, vals[3] * inv);
    *reinterpret_cast<uint2*>(&g_E[(size_t)v * EMB + lane * 4]) = pk.u;  // 8B store, contiguous per warp
}

// ---------------------------------------------------------------------------
// Kernel 2: per-pair compute.
// 16 lanes per pair. Lane l loads uint4 (8 halves) from E[x] and E[y]
// (256B fully-coalesced gather per table), accumulates the two weighted dot
// products, 4-step butterfly reduce within the 16-lane group, lane 0 writes
// sigmoid outputs to out[i] and out[N+i].
// ---------------------------------------------------------------------------
__global__ void pair_kernel(const int* __restrict__ x,
                            const int* __restrict__ y,
                            const float* __restrict__ w1,
                            const float* __restrict__ b1,
                            const float* __restrict__ w2,
                            const float* __restrict__ b2,
                            float* __restrict__ out,
                            int n) {
    int t = blockIdx.x * blockDim.x + threadIdx.x;
    int pair = t >> 4;
    if (pair >= n) return;
    int l = t & 15;

    int xi = __ldg(&x[pair]);
    int yi = __ldg(&y[pair]);

    const uint4* px = reinterpret_cast<const uint4*>(g_E + (size_t)xi * EMB) + l;
    const uint4* py = reinterpret_cast<const uint4*>(g_E + (size_t)yi * EMB) + l;
    uint4 ax = *px;
    uint4 ay = *py;

    // head weights for this lane's 8 dims (two float4 loads each, fully unrolled)
    float wv1[8], wv2[8];
    {
        float4 a = __ldg(reinterpret_cast<const float4*>(w1 + 8 * l));
        float4 c = __ldg(reinterpret_cast<const float4*>(w1 + 8 * l + 4));
        wv1[0] = a.x; wv1[1] = a.y; wv1[2] = a.z; wv1[3] = a.w;
        wv1[4] = c.x; wv1[5] = c.y; wv1[6] = c.z; wv1[7] = c.w;
        float4 d = __ldg(reinterpret_cast<const float4*>(w2 + 8 * l));
        float4 e = __ldg(reinterpret_cast<const float4*>(w2 + 8 * l + 4));
        wv2[0] = d.x; wv2[1] = d.y; wv2[2] = d.z; wv2[3] = d.w;
        wv2[4] = e.x; wv2[5] = e.y; wv2[6] = e.z; wv2[7] = e.w;
    }

    const __half2* hx = reinterpret_cast<const __half2*>(&ax);
    const __half2* hy = reinterpret_cast<const __half2*>(&ay);

    float s1 = 0.f, s2 = 0.f;
#pragma unroll
    for (int k = 0; k < 4; k++) {
        float2 fx = __half22float2(hx[k]);
        float2 fy = __half22float2(hy[k]);
        float p0 = fx.x * fy.x;
        float p1 = fx.y * fy.y;
        s1 = fmaf(p0, wv1[2 * k],     s1);
        s1 = fmaf(p1, wv1[2 * k + 1], s1);
        s2 = fmaf(p0, wv2[2 * k],     s2);
        s2 = fmaf(p1, wv2[2 * k + 1], s2);
    }

    // reduce across the 16-lane group (offsets < 16 keep groups disjoint)
#pragma unroll
    for (int o = 8; o > 0; o >>= 1) {
        s1 += __shfl_xor_sync(0xffffffffu, s1, o);
        s2 += __shfl_xor_sync(0xffffffffu, s2, o);
    }

    if (l == 0) {
        float z1 = s1 + __ldg(b1);
        float z2 = s2 + __ldg(b2);
        out[pair]     = 1.0f / (1.0f + __expf(-z1));
        out[n + pair] = 1.0f / (1.0f + __expf(-z2));
    }
}

extern "C" void kernel_launch(void* const* d_in, const int* in_sizes, int n_in,
                              void* d_out, int out_size) {
    const int*   x  = (const int*)d_in[0];
    const int*   y  = (const int*)d_in[1];
    const float* W  = (const float*)d_in[2];
    const float* b  = (const float*)d_in[3];
    const float* w1 = (const float*)d_in[4];
    const float* b1 = (const float*)d_in[5];
    const float* w2 = (const float*)d_in[6];
    const float* b2 = (const float*)d_in[7];
    float* out = (float*)d_out;
    int n = in_sizes[0];

    // Kernel 1: build normalized fp16 embedding table (recomputed every call —
    // deterministic, input-derived).
    build_table_kernel<<<(VOCAB + 7) / 8, 256>>>(W, b);

    // Kernel 2: per-pair gather + dual weighted dot + sigmoid.
    long long threads = (long long)n * 16;
    int blocks = (int)((threads + 255) / 256);
    pair_kernel<<<blocks, 256>>>(x, y, w1, b1, w2, b2, out, n);
}

// round 6
// speedup vs baseline: 2.3487x; 2.3487x over previous
#include <cuda_runtime.h>
#include <cuda_fp16.h>

#define VOCAB 100000
#define EMB 128

// Normalized embedding table, fp16: E[v][j] = normalize(W[:,v]+b)[j]. 25.6 MB.
__device__ __half g_E[(size_t)VOCAB * EMB];
// Packed fp16 head weights, [chunk q=0..3][lane l=0..7] uint4 (8 halves each).
// q=0: w1 dims 8l..8l+7 ; q=1: w1 dims 64+8l..64+8l+7 ; q=2/3: same for w2.
__device__ uint4 g_Wh[32];

// ---------------------------------------------------------------------------
// Kernel 1: build normalized table via transpose tiles (coalesced W reads).
// Block = 256 threads, handles 32 vocab entries. VOCAB/32 = 3125 exactly.
// ---------------------------------------------------------------------------
__global__ void build_table_kernel(const float* __restrict__ W,
                                   const float* __restrict__ b,
                                   const float* __restrict__ w1,
                                   const float* __restrict__ w2) {
    __shared__ float tile[128][33];   // [dim j][vocab v'], pad 33 => conflict-free cols
    int tid  = threadIdx.x;
    int warp = tid >> 5;
    int lane = tid & 31;
    int v0 = blockIdx.x * 32;

    // Pack head weights once (block 0 only; independent of smem phases).
    if (blockIdx.x == 0 && tid < 8) {
        int l = tid;
        __half h[8];
#pragma unroll
        for (int i = 0; i < 8; i++) h[i] = __float2half(w1[8 * l + i]);
        g_Wh[0 * 8 + l] = *reinterpret_cast<uint4*>(h);
#pragma unroll
        for (int i = 0; i < 8; i++) h[i] = __float2half(w1[64 + 8 * l + i]);
        g_Wh[1 * 8 + l] = *reinterpret_cast<uint4*>(h);
#pragma unroll
        for (int i = 0; i < 8; i++) h[i] = __float2half(w2[8 * l + i]);
        g_Wh[2 * 8 + l] = *reinterpret_cast<uint4*>(h);
#pragma unroll
        for (int i = 0; i < 8; i++) h[i] = __float2half(w2[64 + 8 * l + i]);
        g_Wh[3 * 8 + l] = *reinterpret_cast<uint4*>(h);
    }

    // Load phase: warp w loads dims j = w, w+8, ..., w+120; 128B coalesced rows.
#pragma unroll
    for (int r = 0; r < 16; r++) {
        int j = warp + 8 * r;
        tile[j][lane] = W[(size_t)j * VOCAB + v0 + lane] + __ldg(&b[j]);
    }
    __syncthreads();

    // Compute phase: warp w normalizes vocab entries v' = 4w .. 4w+3.
#pragma unroll
    for (int q = 0; q < 4; q++) {
        int vp = warp * 4 + q;
        float e[4];
        float ss = 0.f;
#pragma unroll
        for (int k = 0; k < 4; k++) {            // dims lane, lane+32, lane+64, lane+96
            e[k] = tile[lane + 32 * k][vp];      // addr stride 33/lane => no conflicts
            ss = fmaf(e[k], e[k], ss);
        }
#pragma unroll
        for (int o = 16; o > 0; o >>= 1)
            ss += __shfl_xor_sync(0xffffffffu, ss, o);
        float inv = 1.0f / fmaxf(sqrtf(ss), 1e-12f);
        __half* row = g_E + (size_t)(v0 + vp) * EMB;
#pragma unroll
        for (int k = 0; k < 4; k++)
            row[lane + 32 * k] = __float2half(e[k] * inv);  // 64B coalesced per k
    }
}

// ---------------------------------------------------------------------------
// Kernel 2: 8 lanes per pair (4 pairs/warp).
// Lane l reads dims [8l..8l+7] and [64+8l..64+8l+7] of E[x] and E[y]
// (each LDG.128 = contiguous 128B per group), HFMA2 against packed weights,
// split butterfly reduce (xor4 -> select -> xor2 -> xor1), lanes 0/4 write.
// ---------------------------------------------------------------------------
__global__ void pair_kernel(const int* __restrict__ x,
                            const int* __restrict__ y,
                            const float* __restrict__ b1,
                            const float* __restrict__ b2,
                            float* __restrict__ out,
                            int n) {
    int t = blockIdx.x * blockDim.x + threadIdx.x;
    int pair = t >> 3;
    if (pair >= n) return;
    int l = t & 7;

    int xi = __ldg(&x[pair]);
    int yi = __ldg(&y[pair]);

    const uint4* rx = reinterpret_cast<const uint4*>(g_E + (size_t)xi * EMB);
    const uint4* ry = reinterpret_cast<const uint4*>(g_E + (size_t)yi * EMB);
    uint4 ax0 = rx[l];          // dims 8l..8l+7
    uint4 ax1 = rx[8 + l];      // dims 64+8l..64+8l+7
    uint4 ay0 = ry[l];
    uint4 ay1 = ry[8 + l];

    uint4 w10 = g_Wh[0 * 8 + l];   // same 128B line for all 4 groups in warp
    uint4 w11 = g_Wh[1 * 8 + l];
    uint4 w20 = g_Wh[2 * 8 + l];
    uint4 w21 = g_Wh[3 * 8 + l];

    const __half2* hx0 = reinterpret_cast<const __half2*>(&ax0);
    const __half2* hx1 = reinterpret_cast<const __half2*>(&ax1);
    const __half2* hy0 = reinterpret_cast<const __half2*>(&ay0);
    const __half2* hy1 = reinterpret_cast<const __half2*>(&ay1);
    const __half2* hw10 = reinterpret_cast<const __half2*>(&w10);
    const __half2* hw11 = reinterpret_cast<const __half2*>(&w11);
    const __half2* hw20 = reinterpret_cast<const __half2*>(&w20);
    const __half2* hw21 = reinterpret_cast<const __half2*>(&w21);

    __half2 s1h = __float2half2_rn(0.f);
    __half2 s2h = __float2half2_rn(0.f);
#pragma unroll
    for (int k = 0; k < 4; k++) {
        __half2 p0 = __hmul2(hx0[k], hy0[k]);
        __half2 p1 = __hmul2(hx1[k], hy1[k]);
        s1h = __hfma2(p0, hw10[k], s1h);
        s1h = __hfma2(p1, hw11[k], s1h);
        s2h = __hfma2(p0, hw20[k], s2h);
        s2h = __hfma2(p1, hw21[k], s2h);
    }
    float s1 = __low2float(s1h) + __high2float(s1h);
    float s2 = __low2float(s2h) + __high2float(s2h);

    // Split reduce over the 8-lane group: after xor4, lanes with (l&4)==0
    // carry head-1 partials, others head-2; finish each 4-lane subgroup.
    s1 += __shfl_xor_sync(0xffffffffu, s1, 4);
    s2 += __shfl_xor_sync(0xffffffffu, s2, 4);
    float s = (l & 4) ? s2 : s1;
    s += __shfl_xor_sync(0xffffffffu, s, 2);
    s += __shfl_xor_sync(0xffffffffu, s, 1);

    if ((l & 3) == 0) {
        bool head1 = (l == 0);
        float z = s + (head1 ? __ldg(b1) : __ldg(b2));
        float o = 1.0f / (1.0f + __expf(-z));
        out[(head1 ? 0 : n) + pair] = o;
    }
}

extern "C" void kernel_launch(void* const* d_in, const int* in_sizes, int n_in,
                              void* d_out, int out_size) {
    const int*   x  = (const int*)d_in[0];
    const int*   y  = (const int*)d_in[1];
    const float* W  = (const float*)d_in[2];
    const float* b  = (const float*)d_in[3];
    const float* w1 = (const float*)d_in[4];
    const float* b1 = (const float*)d_in[5];
    const float* w2 = (const float*)d_in[6];
    const float* b2 = (const float*)d_in[7];
    float* out = (float*)d_out;
    int n = in_sizes[0];

    build_table_kernel<<<VOCAB / 32, 256>>>(W, b, w1, w2);

    long long threads = (long long)n * 8;
    int blocks = (int)((threads + 255) / 256);
    pair_kernel<<<blocks, 256>>>(x, y, b1, b2, out, n);
}